// round 3
// baseline (speedup 1.0000x reference)
#include <cuda_runtime.h>

#define SCALE   0.0625f
#define CC      64
#define HH      200
#define WW      304
#define NROI    512
#define CCHUNK  8
#define NRMAX   37
#define NCMAX   40
// planar per-channel patch: plane stride multiple of 4 (for STS.128 alignment),
// and 1492 mod 32 = 20 -> c*20 mod 32 gives 8 distinct banks for the 8 channel lanes
#define PLS     1492
#define PATCH_ELEMS (CCHUNK * PLS)

__device__ __forceinline__ int iclamp(int v, int lo, int hi) {
    return v < lo ? lo : (v > hi ? hi : v);
}

__global__ void __launch_bounds__(512, 3)
prroi_kernel(const float* __restrict__ feat,
             const float* __restrict__ rois,
             float* __restrict__ out)
{
    extern __shared__ float smem[];
    float* patch = smem;                       // [c][r*40 + x], plane stride 1492
    float* wys   = smem + PATCH_ELEMS;         // 49 (pre-scaled by 1/win)
    float* wxs   = wys + 49;                   // 49
    int*   gys   = (int*)(wxs + 49);           // 49: row offset rel r0, *40
    int*   gxs   = gys + 49;                   // 49: col offset rel x0a

    const int n  = blockIdx.y;
    const int c0 = blockIdx.x * CCHUNK;
    const int t  = threadIdx.x;

    const float* roi = rois + n * 5;
    const int   bi = (int)roi[0];
    const float sx = roi[1] * SCALE, sy = roi[2] * SCALE;
    const float ex = roi[3] * SCALE, ey = roi[4] * SCALE;
    const float ly = fmaxf(ey - sy, 0.f), lx = fmaxf(ex - sx, 0.f);
    const float by = ly * (1.f / 7.f), bx = lx * (1.f / 7.f);

    const int r0  = iclamp((int)floorf(sy), 0, HH - 1);
    const int r1  = iclamp((int)floorf(sy + by * 6.f) + 6, 0, HH - 1);
    const int xlo = iclamp((int)floorf(sx), 0, WW - 1);
    const int xhi = iclamp((int)floorf(sx + bx * 6.f) + 6, 0, WW - 1);
    const int x0a = xlo & ~3;                       // float4-align down
    int nr   = r1 - r0 + 1;            if (nr > NRMAX) nr = NRMAX;
    int ncx4 = (xhi - x0a + 4) >> 2;   if (ncx4 > NCMAX / 4) ncx4 = NCMAX / 4;

    // ---- weights: threads 0..6 -> y axis p, 7..13 -> x axis p ----
    if (t < 14) {
        const bool isx   = t >= 7;
        const int  p     = isx ? t - 7 : t;
        const float start = isx ? sx : sy;
        const float bin   = isx ? bx : by;
        const int   size  = isx ? WW : HH;
        const int   base  = isx ? x0a : r0;

        // fold 1/win into the y weights; win<=0 -> scale 0 -> output 0
        const float win  = bx * by;
        const float wscl = isx ? 1.f : ((win > 0.f) ? 1.f / fmaxf(win, 1e-12f) : 0.f);

        float ws = start + bin * (float)p;
        float we = ws + bin;
        float s  = floorf(ws);
        float Lk[6], Rk[6];
#pragma unroll
        for (int k = 0; k < 6; k++) {
            float cell = s + (float)k;
            bool  act  = cell < we;
            float X0 = fmaxf(ws, cell), X1 = fminf(we, cell + 1.f);
            float a0 = X0 - cell, a1 = X1 - cell;
            Lk[k] = act ? (a1 - 0.5f * a1 * a1 - a0 + 0.5f * a0 * a0) : 0.f;
            float b1v = cell + 1.f - X0, b0v = cell + 1.f - X1;
            Rk[k] = act ? (b1v - 0.5f * b1v * b1v - b0v + 0.5f * b0v * b0v) : 0.f;
        }
        int si = (int)s;
        float* wdst = isx ? wxs : wys;
        int*   gdst = isx ? gxs : gys;
#pragma unroll
        for (int k = 0; k < 7; k++) {
            float w = (k < 6 ? Lk[k] : 0.f) + (k > 0 ? Rk[k - 1] : 0.f);
            int idx = si + k;
            if (idx < 0 || idx >= size) w = 0.f;
            int ic = iclamp(idx, 0, size - 1);
            wdst[p * 7 + k] = w * wscl;
            gdst[p * 7 + k] = isx ? (ic - base) : (ic - base) * NCMAX;
        }
    }

    // ---- stage patch planar: thread = (c = t&7, r = t>>3), xq register loop ----
    // 8*nr <= 296 <= 512 threads; each thread streams one global row with LDG.128.
    {
        const int c = t & (CCHUNK - 1);
        const int r = t >> 3;
        if (r < nr) {
            const float* gp = feat + (((size_t)bi * CC + c0 + c) * HH + (r0 + r)) * (size_t)WW;
            float* sp = patch + c * PLS + r * NCMAX;
            const int nfull = (x0a + 4 * ncx4 - 1 <= xhi) ? ncx4 : ncx4 - 1;
#pragma unroll 4
            for (int xq = 0; xq < nfull; xq++) {
                float4 v = *reinterpret_cast<const float4*>(gp + x0a + 4 * xq);
                *reinterpret_cast<float4*>(sp + 4 * xq) = v;
            }
            if (nfull != ncx4) {          // tail: clamp to avoid OOB at image edge
                int xb = x0a + 4 * nfull;
                float4 v;
                v.x = gp[min(xb,     WW - 1)];
                v.y = gp[min(xb + 1, WW - 1)];
                v.z = gp[min(xb + 2, WW - 1)];
                v.w = gp[min(xb + 3, WW - 1)];
                *reinterpret_cast<float4*>(sp + 4 * nfull) = v;
            }
        }
    }

    __syncthreads();

    // ---- compute: thread = (c = t/49, ij = t%49) -> coalesced STG over ij ----
    if (t < CCHUNK * 49) {
        const int c  = t / 49;
        const int ij = t - 49 * c;
        const int i  = ij / 7;
        const int j  = ij - 7 * i;

        const float* pl = patch + c * PLS;
        float wyv[7], wxv[7];
        int cb[7];
#pragma unroll
        for (int k = 0; k < 7; k++) {
            wyv[k] = wys[i * 7 + k];
            wxv[k] = wxs[j * 7 + k];
            cb[k]  = gxs[j * 7 + k];
        }
        float acc = 0.f;
#pragma unroll
        for (int a = 0; a < 7; a++) {
            const float* row = pl + gys[i * 7 + a];   // already *40
            float srow = 0.f;
#pragma unroll
            for (int b = 0; b < 7; b++)
                srow += wxv[b] * row[cb[b]];
            acc += wyv[a] * srow;
        }
        out[((size_t)n * CC + c0 + c) * 49 + ij] = acc;   // wy pre-scaled by 1/win
    }
}

extern "C" void kernel_launch(void* const* d_in, const int* in_sizes, int n_in,
                              void* d_out, int out_size)
{
    const float* feat = (const float*)d_in[0];
    const float* rois = (const float*)d_in[1];
    float* out = (float*)d_out;

    const int smem_bytes = (PATCH_ELEMS + 49 * 2) * (int)sizeof(float)
                         + 49 * 2 * (int)sizeof(int);   // ~48.2 KB
    cudaFuncSetAttribute(prroi_kernel,
                         cudaFuncAttributeMaxDynamicSharedMemorySize, smem_bytes);
    prroi_kernel<<<dim3(CC / CCHUNK, NROI), 512, smem_bytes>>>(feat, rois, out);
}

// round 4
// speedup vs baseline: 1.1411x; 1.1411x over previous
#include <cuda_runtime.h>

#define SCALE   0.0625f
#define CC      64
#define HH      200
#define WW      304
#define NROI    512
#define CCHUNK  8
#define NRMAX   37
#define NCMAX   40
// planar per-channel patch: plane stride multiple of 4 (for STS.128 alignment),
// 1492*4 bytes mod 128 = 80 -> channel planes de-phased across banks
#define PLS     1492
#define PATCH_ELEMS (CCHUNK * PLS)

__device__ __forceinline__ int iclamp(int v, int lo, int hi) {
    return v < lo ? lo : (v > hi ? hi : v);
}

__global__ void __launch_bounds__(512, 3)
prroi_kernel(const float* __restrict__ feat,
             const float* __restrict__ rois,
             float* __restrict__ out)
{
    extern __shared__ float smem[];
    float* patch = smem;                       // [c][r*40 + x], plane stride 1492
    float* wys   = smem + PATCH_ELEMS;         // 49 (pre-scaled by 1/win)
    float* wxs   = wys + 49;                   // 49
    int*   gys   = (int*)(wxs + 49);           // 49: row offset rel r0, *40
    int*   gxs   = gys + 49;                   // 49: col offset rel x0a

    const int n  = blockIdx.y;
    const int c0 = blockIdx.x * CCHUNK;
    const int t  = threadIdx.x;

    const float* roi = rois + n * 5;
    const int   bi = (int)roi[0];
    const float sx = roi[1] * SCALE, sy = roi[2] * SCALE;
    const float ex = roi[3] * SCALE, ey = roi[4] * SCALE;
    const float ly = fmaxf(ey - sy, 0.f), lx = fmaxf(ex - sx, 0.f);
    const float by = ly * (1.f / 7.f), bx = lx * (1.f / 7.f);

    const int r0  = iclamp((int)floorf(sy), 0, HH - 1);
    const int r1  = iclamp((int)floorf(sy + by * 6.f) + 6, 0, HH - 1);
    const int xlo = iclamp((int)floorf(sx), 0, WW - 1);
    const int xhi = iclamp((int)floorf(sx + bx * 6.f) + 6, 0, WW - 1);
    const int x0a = xlo & ~3;                       // float4-align down
    int nr   = r1 - r0 + 1;            if (nr > NRMAX) nr = NRMAX;
    int ncx4 = (xhi - x0a + 4) >> 2;   if (ncx4 > NCMAX / 4) ncx4 = NCMAX / 4;

    // ---- weights: threads 0..6 -> y axis p, 7..13 -> x axis p ----
    if (t < 14) {
        const bool isx   = t >= 7;
        const int  p     = isx ? t - 7 : t;
        const float start = isx ? sx : sy;
        const float bin   = isx ? bx : by;
        const int   size  = isx ? WW : HH;
        const int   base  = isx ? x0a : r0;

        // fold 1/win into the y weights; win<=0 -> scale 0 -> output 0
        const float win  = bx * by;
        const float wscl = isx ? 1.f : ((win > 0.f) ? 1.f / fmaxf(win, 1e-12f) : 0.f);

        float ws = start + bin * (float)p;
        float we = ws + bin;
        float s  = floorf(ws);
        float Lk[6], Rk[6];
#pragma unroll
        for (int k = 0; k < 6; k++) {
            float cell = s + (float)k;
            bool  act  = cell < we;
            float X0 = fmaxf(ws, cell), X1 = fminf(we, cell + 1.f);
            float a0 = X0 - cell, a1 = X1 - cell;
            Lk[k] = act ? (a1 - 0.5f * a1 * a1 - a0 + 0.5f * a0 * a0) : 0.f;
            float b1v = cell + 1.f - X0, b0v = cell + 1.f - X1;
            Rk[k] = act ? (b1v - 0.5f * b1v * b1v - b0v + 0.5f * b0v * b0v) : 0.f;
        }
        int si = (int)s;
        float* wdst = isx ? wxs : wys;
        int*   gdst = isx ? gxs : gys;
#pragma unroll
        for (int k = 0; k < 7; k++) {
            float w = (k < 6 ? Lk[k] : 0.f) + (k > 0 ? Rk[k - 1] : 0.f);
            int idx = si + k;
            if (idx < 0 || idx >= size) w = 0.f;
            int ic = iclamp(idx, 0, size - 1);
            wdst[p * 7 + k] = w * wscl;
            gdst[p * 7 + k] = isx ? (ic - base) : (ic - base) * NCMAX;
        }
    }

    // ---- stage patch: thread = (q = t%10, r = t/10) [constant divisors],
    //      lanes sweep x within a row -> coalesced LDG.128/STS.128.
    //      channel = unrolled register loop (8 iters, pointer += HH*WW).
    {
        const int q = t % 10;          // constant divisor -> IMAD.HI, cheap
        const int r = t / 10;          // 0..51
        if (r < nr && q < ncx4) {
            const int xb   = x0a + 4 * q;
            const bool tail = (xb + 3 > xhi);
            const float* gp = feat + (((size_t)bi * CC + c0) * HH + (r0 + r)) * (size_t)WW;
            float* sp = patch + r * NCMAX + 4 * q;
#pragma unroll 4
            for (int c = 0; c < CCHUNK; c++) {
                float4 v;
                if (!tail) {
                    v = *reinterpret_cast<const float4*>(gp + xb);
                } else {               // clamp: never read past row/array end
                    v.x = gp[min(xb,     WW - 1)];
                    v.y = gp[min(xb + 1, WW - 1)];
                    v.z = gp[min(xb + 2, WW - 1)];
                    v.w = gp[min(xb + 3, WW - 1)];
                }
                *reinterpret_cast<float4*>(sp) = v;
                gp += (size_t)HH * WW;
                sp += PLS;
            }
        }
    }

    __syncthreads();

    // ---- compute: thread = (c = t/49, ij = t%49) -> coalesced STG over ij ----
    if (t < CCHUNK * 49) {
        const int c  = t / 49;
        const int ij = t - 49 * c;
        const int i  = ij / 7;
        const int j  = ij - 7 * i;

        const float* pl = patch + c * PLS;
        float wyv[7], wxv[7];
        int cb[7];
#pragma unroll
        for (int k = 0; k < 7; k++) {
            wyv[k] = wys[i * 7 + k];
            wxv[k] = wxs[j * 7 + k];
            cb[k]  = gxs[j * 7 + k];
        }
        float acc = 0.f;
#pragma unroll
        for (int a = 0; a < 7; a++) {
            const float* row = pl + gys[i * 7 + a];   // already *40
            float srow = 0.f;
#pragma unroll
            for (int b = 0; b < 7; b++)
                srow += wxv[b] * row[cb[b]];
            acc += wyv[a] * srow;
        }
        out[((size_t)n * CC + c0 + c) * 49 + ij] = acc;   // wy pre-scaled by 1/win
    }
}

extern "C" void kernel_launch(void* const* d_in, const int* in_sizes, int n_in,
                              void* d_out, int out_size)
{
    const float* feat = (const float*)d_in[0];
    const float* rois = (const float*)d_in[1];
    float* out = (float*)d_out;

    const int smem_bytes = (PATCH_ELEMS + 49 * 2) * (int)sizeof(float)
                         + 49 * 2 * (int)sizeof(int);   // ~48.2 KB
    cudaFuncSetAttribute(prroi_kernel,
                         cudaFuncAttributeMaxDynamicSharedMemorySize, smem_bytes);
    prroi_kernel<<<dim3(CC / CCHUNK, NROI), 512, smem_bytes>>>(feat, rois, out);
}